// round 6
// baseline (speedup 1.0000x reference)
#include <cuda_runtime.h>

// VectorQuantizer: z [32768, 64] fp32, codebook [1024, 64] fp32.
// Outputs (float32, concatenated): z_q (2097152) | loss (1) | indices (32768).
//
// d2_k = fl( fl(znorm + cnorm_k) - fl(2 * dot_k) )  -- replicates reference
// rounding composition so argmin matches jnp.argmin (first-min tie-break).
// dot accumulated over k ascending with fp32 rn FMAs (identical per-lane
// sequence to the previously passing kernel; only the SIMD packing changed).

#define NROWS    32768
#define DIM      64
#define KCODES   1024
#define TM       64          // rows per block
#define TN       64          // codes per tile
#define NTILES   (KCODES / TN)
#define NTHREADS 256
#define NBLOCKS  (NROWS / TM)
#define ZSD      66          // float2 stride for duplicated-z smem (16B-aligned rows)
#define CS       68          // float stride for codebook tile smem

#define ZSD_BYTES (DIM * ZSD * 8)            // 33792
#define CS_BYTES  (DIM * CS * 4)             // 17408
#define SMEM_BYTES (ZSD_BYTES + CS_BYTES + TM*4 + TM*4 + 16*4)  // 51776

typedef unsigned long long ull;

__device__ __align__(16) float g_cnorm[KCODES];
__device__ float g_partials[NBLOCKS];

__device__ __forceinline__ void fma2(ull& acc, ull a, ull b) {
    asm("fma.rn.f32x2 %0, %1, %2, %0;" : "+l"(acc) : "l"(a), "l"(b));
}
__device__ __forceinline__ void unpack2(ull v, float& lo, float& hi) {
    asm("mov.b64 {%0, %1}, %2;" : "=f"(lo), "=f"(hi) : "l"(v));
}

// ---------------------------------------------------------------------------
// Kernel 1: codebook row norms. 16 blocks x 64 threads, MLP-16 float4 loads,
// then sequential fp32 add in element order (x,y,z,w ascending) -- identical
// rounding sequence to the elementwise square-then-sum reference.
// ---------------------------------------------------------------------------
__global__ void cnorm_kernel(const float* __restrict__ cb) {
    int k = blockIdx.x * 64 + threadIdx.x;
    const float4* row = (const float4*)(cb + k * DIM);
    float4 v[16];
#pragma unroll
    for (int i = 0; i < 16; i++) v[i] = __ldg(row + i);
    float s = 0.0f;
#pragma unroll
    for (int i = 0; i < 16; i++) {
        s = __fadd_rn(s, __fmul_rn(v[i].x, v[i].x));
        s = __fadd_rn(s, __fmul_rn(v[i].y, v[i].y));
        s = __fadd_rn(s, __fmul_rn(v[i].z, v[i].z));
        s = __fadd_rn(s, __fmul_rn(v[i].w, v[i].w));
    }
    g_cnorm[k] = s;
}

// ---------------------------------------------------------------------------
// Kernel 2: main VQ. Each block: 64 rows x 1024 codes.
// Thread (tx, ty): rows ty*4..ty*4+3, codes tile*64 + tx*4..tx*4+3.
// z duplicated in smem as float2{z,z} (written once); codebook tiles read as
// native float4 -> two packed {c0,c1},{c2,c3} operands. No packs in the loop:
// per k = 2 LDS.128(z, broadcast) + 1 LDS.128(c) + 8 FFMA2.
// ---------------------------------------------------------------------------
__global__ __launch_bounds__(NTHREADS, 3)
void vq_kernel(const float* __restrict__ z,
               const float* __restrict__ codebook,
               float* __restrict__ out) {
    extern __shared__ char smem_raw[];
    float2* zsD    = (float2*)smem_raw;                          // [DIM][ZSD]
    float*  csT    = (float*)(smem_raw + ZSD_BYTES);             // [DIM][CS]
    float*  znorm_s = (float*)(smem_raw + ZSD_BYTES + CS_BYTES); // [TM]
    int*    ridx_s  = (int*)(znorm_s + TM);                      // [TM]
    float*  lsum_s  = (float*)(ridx_s + TM);                     // [16]

    const int tid = threadIdx.x;
    const int tx = tid & 15;            // code group
    const int ty = tid >> 4;            // row group
    const int rowBase = blockIdx.x * TM;

    // ---- load z tile (coalesced), store transposed + duplicated ----
#pragma unroll
    for (int i = 0; i < 16; i++) {
        int flat = i * NTHREADS + tid;
        int r = flat >> 6, d = flat & 63;
        float v = z[(rowBase + r) * DIM + d];
        zsD[d * ZSD + r] = make_float2(v, v);
    }
    __syncthreads();

    // ---- row norms: square (rounded) then sequential add, ascending d ----
    if (tid < TM) {
        float s = 0.0f;
#pragma unroll
        for (int d = 0; d < DIM; d++) {
            float v = zsD[d * ZSD + tid].x;
            s = __fadd_rn(s, __fmul_rn(v, v));
        }
        znorm_s[tid] = s;
    }
    __syncthreads();

    float zn[4];
#pragma unroll
    for (int r = 0; r < 4; r++) zn[r] = znorm_s[(ty << 2) + r];

    float minval[4] = {3.4e38f, 3.4e38f, 3.4e38f, 3.4e38f};
    int   minidx[4] = {0, 0, 0, 0};

    // ---- prefetch tile 0 (codebook tile + its cnorms) into registers ----
    float pf[16];
    float4 pfcn;
    {
        const float* src = codebook;   // cbase = 0
#pragma unroll
        for (int i = 0; i < 16; i++) pf[i] = __ldg(src + i * NTHREADS + tid);
        pfcn = __ldg((const float4*)g_cnorm + tx);
    }

    for (int t = 0; t < NTILES; t++) {
        const int cbase = t * TN;

        __syncthreads();   // all warps done reading csT from previous tile
        // store prefetched tile transposed: flat = cl*64 + d
#pragma unroll
        for (int i = 0; i < 16; i++) {
            int flat = i * NTHREADS + tid;
            csT[(flat & 63) * CS + (flat >> 6)] = pf[i];
        }
        float4 cn = pfcn;
        __syncthreads();   // csT ready

        // issue next tile's loads; consumed after the k-loop below
        if (t + 1 < NTILES) {
            const float* src = codebook + (cbase + TN) * DIM;
#pragma unroll
            for (int i = 0; i < 16; i++) pf[i] = __ldg(src + i * NTHREADS + tid);
            pfcn = __ldg((const float4*)g_cnorm + ((cbase + TN) >> 2) + tx);
        }

        // acc[r][cp]: packed over code pairs {c0,c1} / {c2,c3}
        ull acc[4][2];
#pragma unroll
        for (int r = 0; r < 4; r++) { acc[r][0] = 0ull; acc[r][1] = 0ull; }

#pragma unroll 16
        for (int k = 0; k < DIM; k++) {
            const ull* zp = (const ull*)(zsD + k * ZSD + (ty << 2));
            ull zd0 = zp[0];           // {z[r0], z[r0]}
            ull zd1 = zp[1];
            ull zd2 = zp[2];
            ull zd3 = zp[3];
            float4 cv = *(const float4*)(csT + k * CS + (tx << 2));
            ull c01 = ((const ull*)&cv)[0];   // {c0, c1}
            ull c23 = ((const ull*)&cv)[1];   // {c2, c3}
            fma2(acc[0][0], zd0, c01); fma2(acc[0][1], zd0, c23);
            fma2(acc[1][0], zd1, c01); fma2(acc[1][1], zd1, c23);
            fma2(acc[2][0], zd2, c01); fma2(acc[2][1], zd2, c23);
            fma2(acc[3][0], zd3, c01); fma2(acc[3][1], zd3, c23);
        }

        // epilogue: dist = fl( fl(znorm + cnorm) - fl(2*dot) ), codes ascending
#pragma unroll
        for (int cp = 0; cp < 2; cp++) {
            int code0 = cbase + (tx << 2) + cp * 2;
            float cn0 = (cp == 0) ? cn.x : cn.z;
            float cn1 = (cp == 0) ? cn.y : cn.w;
#pragma unroll
            for (int r = 0; r < 4; r++) {
                float dlo, dhi;
                unpack2(acc[r][cp], dlo, dhi);
                float d0 = __fsub_rn(__fadd_rn(zn[r], cn0), __fmul_rn(2.0f, dlo));
                if (d0 < minval[r]) { minval[r] = d0; minidx[r] = code0; }
                float d1 = __fsub_rn(__fadd_rn(zn[r], cn1), __fmul_rn(2.0f, dhi));
                if (d1 < minval[r]) { minval[r] = d1; minidx[r] = code0 + 1; }
            }
        }
    }

    // ---- cross-lane reduction over the 16 code-lanes (same ty group) ----
#pragma unroll
    for (int r = 0; r < 4; r++) {
#pragma unroll
        for (int m = 8; m >= 1; m >>= 1) {
            float ov = __shfl_xor_sync(0xffffffffu, minval[r], m);
            int   oi = __shfl_xor_sync(0xffffffffu, minidx[r], m);
            if (ov < minval[r] || (ov == minval[r] && oi < minidx[r])) {
                minval[r] = ov; minidx[r] = oi;
            }
        }
    }

    __syncthreads();   // csT no longer needed; reuse sync before result stores
    if (tx == 0) {
        float s = 0.0f;
#pragma unroll
        for (int r = 0; r < 4; r++) {
            ridx_s[(ty << 2) + r] = minidx[r];
            s = __fadd_rn(s, minval[r]);   // = ||z_r - c_idx||^2
        }
        lsum_s[ty] = s;
    }
    __syncthreads();

    if (tid == 0) {
        float s = 0.0f;
#pragma unroll
        for (int i = 0; i < 16; i++) s = __fadd_rn(s, lsum_s[i]);
        g_partials[blockIdx.x] = s;
    }

    // ---- write indices (as float) ----
    if (tid < TM) {
        out[NROWS * DIM + 1 + rowBase + tid] = (float)ridx_s[tid];
    }

    // ---- write z_q = codebook[idx] (coalesced) ----
#pragma unroll
    for (int i = 0; i < 16; i++) {
        int flat = i * NTHREADS + tid;
        int r = flat >> 6, c = flat & 63;
        out[(rowBase + r) * DIM + c] = codebook[ridx_s[r] * DIM + c];
    }
}

// ---------------------------------------------------------------------------
// Kernel 3: deterministic loss reduce.
// loss = mean + 0.25*mean, mean = sum(||z - z_q||^2) / (N*D)
// ---------------------------------------------------------------------------
__global__ void loss_kernel(float* __restrict__ out) {
    __shared__ float s[NBLOCKS];
    int tid = threadIdx.x;
    s[tid] = g_partials[tid];
    __syncthreads();
    for (int m = NBLOCKS / 2; m > 0; m >>= 1) {
        if (tid < m) s[tid] = __fadd_rn(s[tid], s[tid + m]);
        __syncthreads();
    }
    if (tid == 0) {
        float mean = s[0] / (float)(NROWS * DIM);   // /2^21: exact
        out[NROWS * DIM] = __fadd_rn(mean, __fmul_rn(0.25f, mean));
    }
}

extern "C" void kernel_launch(void* const* d_in, const int* in_sizes, int n_in,
                              void* d_out, int out_size) {
    const float* z        = (const float*)d_in[0];
    const float* codebook = (const float*)d_in[1];
    float* out = (float*)d_out;

    static int attr_done = 0;
    if (!attr_done) {
        cudaFuncSetAttribute(vq_kernel,
                             cudaFuncAttributeMaxDynamicSharedMemorySize,
                             SMEM_BYTES);
        attr_done = 1;
    }

    cnorm_kernel<<<KCODES / 64, 64>>>(codebook);
    vq_kernel<<<NBLOCKS, NTHREADS, SMEM_BYTES>>>(z, codebook, out);
    loss_kernel<<<1, NBLOCKS>>>(out);
}